// round 14
// baseline (speedup 1.0000x reference)
#include <cuda_runtime.h>

// Shape (B=2, C=1, D=160, H=192, W=224), win=5, eps=1e-8
#define DD 160
#define HH 192
#define WW 224
#define BB 2
#define HW (HH * WW)
#define TX 32
#define TY 12
#define RR 16                    // rows per block = TY + 4
#define RCOLS 36                 // halo cols = TX + 4
#define GX (WW / TX)             // 7
#define GY (HH / TY)             // 16
#define NBLOCKS 888              // == 296 * 3 : exact multiple of chip concurrency
#define NT 512
#define NTOT ((double)BB * DD * HH * WW)

// dynamic smem layout (bytes)
#define RAW_PAIR_BYTES 9216                    // float2 [2][RR][RCOLS]
#define RAW_SLICE_BYTES 4608                   // float2 [RR][RCOLS]
#define OFF_RAW   0                            // float2 [2][2][RR][RCOLS] = 18432
#define OFF_ZS4   18432                        // float4 [2][2][RR][TX]   = 32768
#define OFF_ZS1   (18432 + 32768)              // float  [2][2][RR][TX]   = 8192
#define OFF_SRED  (18432 + 32768 + 8192)       // double [16]             = 128
#define OFF_LAST  (OFF_SRED + 128)             // int
#define SMEM_BYTES (OFF_LAST + 16)

__device__ double g_partials[NBLOCKS];
__device__ unsigned int g_count = 0;

// 4-byte async copy global->shared with zero-fill when pred is false
__device__ __forceinline__ void cpa4(unsigned dst, const float* src, bool pred)
{
    const int sz = pred ? 4 : 0;
    asm volatile("cp.async.ca.shared.global [%0], [%1], 4, %2;"
                 :: "r"(dst), "l"(src), "r"(sz) : "memory");
}
__device__ __forceinline__ void cpa_wait_all()
{
    asm volatile("cp.async.wait_all;" ::: "memory");
}

__device__ __forceinline__ float ncc_cc(float4 s, float sij)
{
    const float wsz = 125.0f, inv = 1.0f / 125.0f;
    const float uI = s.x * inv, uJ = s.y * inv;
    const float cross = sij - uJ * s.x - uI * s.y + uI * uJ * wsz;
    const float Iv = s.z - 2.0f * uI * s.x + uI * uI * wsz;
    const float Jv = s.w - 2.0f * uJ * s.y + uJ * uJ * wsz;
    return __fdividef(cross * cross, Iv * Jv + 1e-8f);
}

// x-box sums + z-ring update for one slice S (0/1) of current pair bi.
#define XR(SLOT, S) do {                                                        \
    float2 v0 = sraw[bi][S][xr][xx + 0];                                        \
    float2 v1 = sraw[bi][S][xr][xx + 1];                                        \
    float2 v2 = sraw[bi][S][xr][xx + 2];                                        \
    float2 v3 = sraw[bi][S][xr][xx + 3];                                        \
    float2 v4 = sraw[bi][S][xr][xx + 4];                                        \
    const float a0 = v0.x + v1.x + v2.x + v3.x + v4.x;                          \
    const float a1 = v0.y + v1.y + v2.y + v3.y + v4.y;                          \
    const float a2 = fmaf(v4.x, v4.x, fmaf(v3.x, v3.x,                          \
                     fmaf(v2.x, v2.x, fmaf(v1.x, v1.x, v0.x * v0.x))));         \
    const float a3 = fmaf(v4.y, v4.y, fmaf(v3.y, v3.y,                          \
                     fmaf(v2.y, v2.y, fmaf(v1.y, v1.y, v0.y * v0.y))));         \
    const float a4 = fmaf(v4.x, v4.y, fmaf(v3.x, v3.y,                          \
                     fmaf(v2.x, v2.y, fmaf(v1.x, v1.y, v0.x * v0.y))));         \
    SI  += a0 - r0[SLOT]; r0[SLOT] = a0;                                        \
    SJ  += a1 - r1[SLOT]; r1[SLOT] = a1;                                        \
    SII += a2 - r2[SLOT]; r2[SLOT] = a2;                                        \
    SJJ += a3 - r3[SLOT]; r3[SLOT] = a3;                                        \
    SIJ += a4 - r4[SLOT]; r4[SLOT] = a4;                                        \
    zs4[bi][S][xr][xx] = make_float4(SI, SJ, SII, SJJ);                         \
    zs1[bi][S][xr][xx] = SIJ;                                                   \
} while (0)

// One phase = two z-slices, one barrier. SA/SB/DOY compile-time literals.
#define PHASE(SA, SB, DOY) do {                                                 \
    {   /* async fill of pair bi^1 with slices (zpre, zpre+1), zfill OOB */     \
        const bool zA = (zpre < DD), zB = (zpre + 1 < DD);                      \
        const unsigned dA0 = raw_u32 + (bi ^ 1) * RAW_PAIR_BYTES + e0off;       \
        const unsigned dB0 = dA0 + RAW_SLICE_BYTES;                             \
        const float* sI0 = gI + pB0 + preoff;                                   \
        const float* sJ0 = gJ + pB0 + preoff;                                   \
        cpa4(dA0,     sI0,      zA && ok0);                                     \
        cpa4(dA0 + 4, sJ0,      zA && ok0);                                     \
        cpa4(dB0,     sI0 + HW, zB && ok0);                                     \
        cpa4(dB0 + 4, sJ0 + HW, zB && ok0);                                     \
        if (has1) {                                                             \
            const unsigned dA1 = raw_u32 + (bi ^ 1) * RAW_PAIR_BYTES + e1off;   \
            const unsigned dB1 = dA1 + RAW_SLICE_BYTES;                         \
            const float* sI1 = gI + pB1 + preoff;                               \
            const float* sJ1 = gJ + pB1 + preoff;                               \
            cpa4(dA1,     sI1,      zA && ok1);                                 \
            cpa4(dA1 + 4, sJ1,      zA && ok1);                                 \
            cpa4(dB1,     sI1 + HW, zB && ok1);                                 \
            cpa4(dB1 + 4, sJ1 + HW, zB && ok1);                                 \
        }                                                                       \
    }                                                                           \
    float w0 = 0.f, w1 = 0.f, w2 = 0.f;                                         \
    if (DOY) { w0 = gW[woff]; w1 = gW[woff + WW]; w2 = gW[woff + 2 * WW]; }     \
    XR(SA, 0);                                                                  \
    XR(SB, 1);                                                                  \
    cpa_wait_all();                                                             \
    __syncthreads();                                                            \
    if (DOY) {                                                                  \
        /* streamed 3-output y-window over 7 rows (half-warp, 16 cols) */       \
        float4 S0, S1, S2; float T0, T1, T2;                                    \
        _Pragma("unroll")                                                       \
        for (int j = 0; j < 7; ++j) {                                           \
            float4 v = zs4[bi][esl][g3 + j][ecol];                              \
            float  u = zs1[bi][esl][g3 + j][ecol];                              \
            if (j == 0) { S0 = v; T0 = u; }                                     \
            else if (j < 5) { S0.x += v.x; S0.y += v.y; S0.z += v.z;            \
                              S0.w += v.w; T0 += u; }                           \
            if (j == 1) { S1 = v; T1 = u; }                                     \
            else if (j > 1 && j < 6) { S1.x += v.x; S1.y += v.y; S1.z += v.z;   \
                                       S1.w += v.w; T1 += u; }                  \
            if (j == 2) { S2 = v; T2 = u; }                                     \
            else if (j > 2) { S2.x += v.x; S2.y += v.y; S2.z += v.z;            \
                              S2.w += v.w; T2 += u; }                           \
        }                                                                       \
        const float c0 = ncc_cc(S0, T0);                                        \
        const float c1 = ncc_cc(S1, T1);                                        \
        const float c2 = ncc_cc(S2, T2);                                        \
        if (emit_lane)                                                          \
            acc = fmaf(c0, w0, fmaf(c1, w1, fmaf(c2, w2, acc)));                \
        woff += 2 * HW;                                                         \
    }                                                                           \
    bi ^= 1; zpre += 2; preoff += 2 * HW;                                       \
} while (0)

__global__ __launch_bounds__(NT, 2)
void ncc_fused(const float* __restrict__ gI,
               const float* __restrict__ gJ,
               const float* __restrict__ gW,
               float* __restrict__ out)
{
    extern __shared__ unsigned char dsm[];
    float2 (*sraw)[2][RR][RCOLS] = (float2 (*)[2][RR][RCOLS])(dsm + OFF_RAW);
    float4 (*zs4)[2][RR][TX]     = (float4 (*)[2][RR][TX])(dsm + OFF_ZS4);
    float  (*zs1)[2][RR][TX]     = (float  (*)[2][RR][TX])(dsm + OFF_ZS1);
    double* sred  = (double*)(dsm + OFF_SRED);
    int*    slast = (int*)(dsm + OFF_LAST);

    const int tid  = threadIdx.x;
    const int lane = tid & 31;
    const int warp = tid >> 5;

    // ---- block schedule decode: 888 blocks over 224 (x,y,b) columns ----
    // blocks 0..23  : 8 special columns x 3 chunks, z0={0,60,110}, len={60,50,50}
    // blocks 24..887: 216 regular columns x 4 chunks of len 40
    const int bid = blockIdx.x;
    int c, z0, ngrp;                      // ngrp = npairs/5
    if (bid < 24) {
        c = bid / 3;
        const int ci = bid - c * 3;
        z0   = (ci == 0) ? 0 : (ci == 1 ? 60 : 110);
        ngrp = (ci == 0) ? 6 : 5;         // 30 / 25 / 25 pairs
    } else {
        const int q = bid - 24;
        c = 8 + (q >> 2);
        const int ci = q & 3;
        z0 = ci * 40;
        ngrp = 4;                         // 20 pairs
    }
    const int b  = c / (GX * GY);
    const int rr = c - b * (GX * GY);
    const int yt = rr / GX;
    const int xt = rr - yt * GX;
    const int x0 = xt * TX;
    const int y0 = yt * TY;
    const int base = b * (DD * HW);

    // shared-state u32 base for cp.async destinations
    unsigned raw_u32;
    {
        unsigned long long p = (unsigned long long)__cvta_generic_to_shared(dsm + OFF_RAW);
        raw_u32 = (unsigned)p;
    }

    // ---- raw loader mapping: 576 entries over 512 threads ----
    const int row0 = tid / RCOLS, col0 = tid - row0 * RCOLS;
    const int gy0 = y0 + row0 - 2, gx0 = x0 + col0 - 2;
    const bool ok0 = ((unsigned)gy0 < HH) && ((unsigned)gx0 < WW);
    const int pB0 = base + (ok0 ? gy0 * WW + gx0 : 0);
    const unsigned e0off = (unsigned)(row0 * RCOLS + col0) * 8u;

    const bool has1 = (tid < RR * RCOLS - NT);    // 64 extra entries
    const int e1 = tid + NT;
    const int row1 = e1 / RCOLS, col1 = e1 - row1 * RCOLS;
    const int gy1 = y0 + row1 - 2, gx1 = x0 + col1 - 2;
    const bool ok1 = ((unsigned)gy1 < HH) && ((unsigned)gx1 < WW);
    const int pB1 = base + (ok1 ? gy1 * WW + gx1 : 0);
    const unsigned e1off = (unsigned)(row1 * RCOLS + col1) * 8u;

    // ---- xsum entry: one (row, x) per thread ----
    const int xr = warp;            // 0..15
    const int xx = lane;            // 0..31

    // ---- y-emit mapping: ALL 16 warps, half-active ----
    // warp = (slice[1] | rowgroup[2] | colhalf[1]); lanes 16-31 duplicate 0-15.
    const int esl   = warp >> 3;                  // slice of the pair
    const int g3    = ((warp >> 1) & 3) * 3;      // output rows g3..g3+2
    const int ecol  = ((warp & 1) << 4) + (lane & 15);  // col 0..31
    const bool emit_lane = (lane < 16);
    int woff = base + (z0 + esl) * HW + (y0 + g3) * WW + (x0 + ecol);

    // ---- z ring (static slots) + running sums ----
    float r0[5] = {0,0,0,0,0}, r1[5] = {0,0,0,0,0}, r2[5] = {0,0,0,0,0};
    float r3[5] = {0,0,0,0,0}, r4[5] = {0,0,0,0,0};
    float SI = 0.f, SJ = 0.f, SII = 0.f, SJJ = 0.f, SIJ = 0.f;
    float acc = 0.f;

    // ---- prologue: slices z0-2, z0-1 into pair 0 (async + wait + barrier) ----
    {
        const int zp = z0 - 2;
        const bool zA = (zp >= 0);
        const bool zB = (zp + 1 >= 0);
        const unsigned dA0 = raw_u32 + e0off;
        const unsigned dB0 = dA0 + RAW_SLICE_BYTES;
        const float* sI0 = gI + pB0 + zp * HW;
        const float* sJ0 = gJ + pB0 + zp * HW;
        cpa4(dA0,     sI0,      zA && ok0);
        cpa4(dA0 + 4, sJ0,      zA && ok0);
        cpa4(dB0,     sI0 + HW, zB && ok0);
        cpa4(dB0 + 4, sJ0 + HW, zB && ok0);
        if (has1) {
            const unsigned dA1 = raw_u32 + e1off;
            const unsigned dB1 = dA1 + RAW_SLICE_BYTES;
            const float* sI1 = gI + pB1 + zp * HW;
            const float* sJ1 = gJ + pB1 + zp * HW;
            cpa4(dA1,     sI1,      zA && ok1);
            cpa4(dA1 + 4, sJ1,      zA && ok1);
            cpa4(dB1,     sI1 + HW, zB && ok1);
            cpa4(dB1 + 4, sJ1 + HW, zB && ok1);
        }
        cpa_wait_all();
        __syncthreads();
    }

    int bi = 0;
    int zpre = z0;               // phase p prefetches slices z0+2p, z0+2p+1
    int preoff = z0 * HW;

    PHASE(0, 1, false);          // XR z0-2, z0-1
    PHASE(2, 3, false);          // XR z0,   z0+1

    // ---- main: ngrp statically-unrolled 5-phase groups (period = 10 slices) ----
#pragma unroll 1
    for (int g = 0; g < ngrp; ++g) {
        PHASE(4, 0, true);
        PHASE(1, 2, true);
        PHASE(3, 4, true);
        PHASE(0, 1, true);
        PHASE(2, 3, true);
    }

    // ---- reduction: shuffle tree (deterministic) ----
    double a = (double)acc;
#pragma unroll
    for (int off = 16; off > 0; off >>= 1)
        a += __shfl_down_sync(0xffffffffu, a, off);
    if (lane == 0) sred[warp] = a;
    __syncthreads();
    if (warp == 0) {
        double s = (lane < 16) ? sred[lane] : 0.0;
#pragma unroll
        for (int off = 8; off > 0; off >>= 1)
            s += __shfl_down_sync(0xffffffffu, s, off);
        if (lane == 0) {
            g_partials[bid] = s;
            __threadfence();
            const unsigned v = atomicAdd(&g_count, 1u);
            *slast = (v == NBLOCKS - 1);
        }
    }
    __syncthreads();

    // ---- last block folds all partials in fixed order ----
    if (*slast) {
        double s = 0.0;
        for (int i = tid; i < NBLOCKS; i += NT) s += g_partials[i];
#pragma unroll
        for (int off = 16; off > 0; off >>= 1)
            s += __shfl_down_sync(0xffffffffu, s, off);
        if (lane == 0) sred[warp] = s;
        __syncthreads();
        if (warp == 0) {
            double t = (lane < 16) ? sred[lane] : 0.0;
#pragma unroll
            for (int off = 8; off > 0; off >>= 1)
                t += __shfl_down_sync(0xffffffffu, t, off);
            if (lane == 0) {
                out[0] = (float)(-t / NTOT);
                g_count = 0;   // reset for next graph replay
            }
        }
    }
}

extern "C" void kernel_launch(void* const* d_in, const int* in_sizes, int n_in,
                              void* d_out, int out_size)
{
    const float* I  = (const float*)d_in[0];
    const float* J  = (const float*)d_in[1];
    const float* Wt = (const float*)d_in[2];
    float* out = (float*)d_out;

    cudaFuncSetAttribute(ncc_fused, cudaFuncAttributeMaxDynamicSharedMemorySize,
                         SMEM_BYTES);
    ncc_fused<<<NBLOCKS, NT, SMEM_BYTES>>>(I, J, Wt, out);
}

// round 16
// speedup vs baseline: 1.2470x; 1.2470x over previous
#include <cuda_runtime.h>

// Shape (B=2, C=1, D=160, H=192, W=224), win=5, eps=1e-8
#define DD 160
#define HH 192
#define WW 224
#define BB 2
#define HW (HH * WW)
#define TX 32
#define TY 12
#define RR 16                    // rows per block = TY + 4
#define RCOLS 36                 // halo cols = TX + 4
#define GX (WW / TX)             // 7
#define GY (HH / TY)             // 16
#define NBLOCKS 888              // == 296 * 3 : exact multiple of chip concurrency
#define NT 512
#define NTOT ((double)BB * DD * HH * WW)

// dynamic smem layout (bytes)
#define RAW_PAIR_BYTES 9216                    // float2 [2][RR][RCOLS]
#define RAW_SLICE_BYTES 4608                   // float2 [RR][RCOLS]
#define OFF_RAW   0                            // float2 [2][2][RR][RCOLS] = 18432
#define OFF_ZS4   18432                        // float4 [2][2][RR][TX]   = 32768
#define OFF_ZS1   (18432 + 32768)              // float  [2][2][RR][TX]   = 8192
#define OFF_SRED  (18432 + 32768 + 8192)       // double [16]             = 128
#define OFF_LAST  (OFF_SRED + 128)             // int
#define SMEM_BYTES (OFF_LAST + 16)

__device__ double g_partials[NBLOCKS];
__device__ unsigned int g_count = 0;

// 4-byte async copy global->shared with zero-fill when pred is false
__device__ __forceinline__ void cpa4(unsigned dst, const float* src, bool pred)
{
    const int sz = pred ? 4 : 0;
    asm volatile("cp.async.ca.shared.global [%0], [%1], 4, %2;"
                 :: "r"(dst), "l"(src), "r"(sz) : "memory");
}
__device__ __forceinline__ void cpa_wait_all()
{
    asm volatile("cp.async.wait_all;" ::: "memory");
}

__device__ __forceinline__ float ncc_cc(float4 s, float sij)
{
    const float wsz = 125.0f, inv = 1.0f / 125.0f;
    const float uI = s.x * inv, uJ = s.y * inv;
    const float cross = sij - uJ * s.x - uI * s.y + uI * uJ * wsz;
    const float Iv = s.z - 2.0f * uI * s.x + uI * uI * wsz;
    const float Jv = s.w - 2.0f * uJ * s.y + uJ * uJ * wsz;
    return __fdividef(cross * cross, Iv * Jv + 1e-8f);
}

// x-box sums + z-ring update for one slice S (0/1) of current pair bi.
#define XR(SLOT, S) do {                                                        \
    float2 v0 = sraw[bi][S][xr][xx + 0];                                        \
    float2 v1 = sraw[bi][S][xr][xx + 1];                                        \
    float2 v2 = sraw[bi][S][xr][xx + 2];                                        \
    float2 v3 = sraw[bi][S][xr][xx + 3];                                        \
    float2 v4 = sraw[bi][S][xr][xx + 4];                                        \
    const float a0 = v0.x + v1.x + v2.x + v3.x + v4.x;                          \
    const float a1 = v0.y + v1.y + v2.y + v3.y + v4.y;                          \
    const float a2 = fmaf(v4.x, v4.x, fmaf(v3.x, v3.x,                          \
                     fmaf(v2.x, v2.x, fmaf(v1.x, v1.x, v0.x * v0.x))));         \
    const float a3 = fmaf(v4.y, v4.y, fmaf(v3.y, v3.y,                          \
                     fmaf(v2.y, v2.y, fmaf(v1.y, v1.y, v0.y * v0.y))));         \
    const float a4 = fmaf(v4.x, v4.y, fmaf(v3.x, v3.y,                          \
                     fmaf(v2.x, v2.y, fmaf(v1.x, v1.y, v0.x * v0.y))));         \
    SI  += a0 - r0[SLOT]; r0[SLOT] = a0;                                        \
    SJ  += a1 - r1[SLOT]; r1[SLOT] = a1;                                        \
    SII += a2 - r2[SLOT]; r2[SLOT] = a2;                                        \
    SJJ += a3 - r3[SLOT]; r3[SLOT] = a3;                                        \
    SIJ += a4 - r4[SLOT]; r4[SLOT] = a4;                                        \
    zs4[bi][S][xr][xx] = make_float4(SI, SJ, SII, SJJ);                         \
    zs1[bi][S][xr][xx] = SIJ;                                                   \
} while (0)

// One phase = two z-slices, one barrier. SA/SB/DOY compile-time literals.
#define PHASE(SA, SB, DOY) do {                                                 \
    {   /* async fill of pair bi^1 with slices (zpre, zpre+1), zfill OOB */     \
        const bool zA = (zpre < DD), zB = (zpre + 1 < DD);                      \
        const unsigned dA0 = raw_u32 + (bi ^ 1) * RAW_PAIR_BYTES + e0off;       \
        const unsigned dB0 = dA0 + RAW_SLICE_BYTES;                             \
        const float* sI0 = gI + pB0 + preoff;                                   \
        const float* sJ0 = gJ + pB0 + preoff;                                   \
        cpa4(dA0,     sI0,      zA && ok0);                                     \
        cpa4(dA0 + 4, sJ0,      zA && ok0);                                     \
        cpa4(dB0,     sI0 + HW, zB && ok0);                                     \
        cpa4(dB0 + 4, sJ0 + HW, zB && ok0);                                     \
        if (has1) {                                                             \
            const unsigned dA1 = raw_u32 + (bi ^ 1) * RAW_PAIR_BYTES + e1off;   \
            const unsigned dB1 = dA1 + RAW_SLICE_BYTES;                         \
            const float* sI1 = gI + pB1 + preoff;                               \
            const float* sJ1 = gJ + pB1 + preoff;                               \
            cpa4(dA1,     sI1,      zA && ok1);                                 \
            cpa4(dA1 + 4, sJ1,      zA && ok1);                                 \
            cpa4(dB1,     sI1 + HW, zB && ok1);                                 \
            cpa4(dB1 + 4, sJ1 + HW, zB && ok1);                                 \
        }                                                                       \
    }                                                                           \
    float w0 = 0.f, w1 = 0.f, w2 = 0.f;                                         \
    if (DOY && emit_ok) {                                                       \
        w0 = gW[woff]; w1 = gW[woff + WW]; w2 = gW[woff + 2 * WW];              \
    }                                                                           \
    XR(SA, 0);                                                                  \
    XR(SB, 1);                                                                  \
    cpa_wait_all();                                                             \
    __syncthreads();                                                            \
    if (DOY && emit_ok) {                                                       \
        /* streamed 3-output y-window over 7 rows, 8 full warps */              \
        float4 S0, S1, S2; float T0, T1, T2;                                    \
        _Pragma("unroll")                                                       \
        for (int j = 0; j < 7; ++j) {                                           \
            float4 v = zs4[bi][esl][g3 + j][exx];                               \
            float  u = zs1[bi][esl][g3 + j][exx];                               \
            if (j == 0) { S0 = v; T0 = u; }                                     \
            else if (j < 5) { S0.x += v.x; S0.y += v.y; S0.z += v.z;            \
                              S0.w += v.w; T0 += u; }                           \
            if (j == 1) { S1 = v; T1 = u; }                                     \
            else if (j > 1 && j < 6) { S1.x += v.x; S1.y += v.y; S1.z += v.z;   \
                                       S1.w += v.w; T1 += u; }                  \
            if (j == 2) { S2 = v; T2 = u; }                                     \
            else if (j > 2) { S2.x += v.x; S2.y += v.y; S2.z += v.z;            \
                              S2.w += v.w; T2 += u; }                           \
        }                                                                       \
        acc = fmaf(ncc_cc(S0, T0), w0, acc);                                    \
        acc = fmaf(ncc_cc(S1, T1), w1, acc);                                    \
        acc = fmaf(ncc_cc(S2, T2), w2, acc);                                    \
        woff += 2 * HW;                                                         \
    }                                                                           \
    bi ^= 1; zpre += 2; preoff += 2 * HW;                                       \
} while (0)

__global__ __launch_bounds__(NT, 2)
void ncc_fused(const float* __restrict__ gI,
               const float* __restrict__ gJ,
               const float* __restrict__ gW,
               float* __restrict__ out)
{
    extern __shared__ unsigned char dsm[];
    float2 (*sraw)[2][RR][RCOLS] = (float2 (*)[2][RR][RCOLS])(dsm + OFF_RAW);
    float4 (*zs4)[2][RR][TX]     = (float4 (*)[2][RR][TX])(dsm + OFF_ZS4);
    float  (*zs1)[2][RR][TX]     = (float  (*)[2][RR][TX])(dsm + OFF_ZS1);
    double* sred  = (double*)(dsm + OFF_SRED);
    int*    slast = (int*)(dsm + OFF_LAST);

    const int tid  = threadIdx.x;
    const int lane = tid & 31;
    const int warp = tid >> 5;

    // ---- block schedule decode: 888 blocks over 224 (x,y,b) columns ----
    // blocks 0..23  : 8 special columns x 3 chunks, z0={0,60,110}, len={60,50,50}
    // blocks 24..887: 216 regular columns x 4 chunks of len 40
    const int bid = blockIdx.x;
    int c, z0, ngrp;                      // ngrp = npairs/5
    if (bid < 24) {
        c = bid / 3;
        const int ci = bid - c * 3;
        z0   = (ci == 0) ? 0 : (ci == 1 ? 60 : 110);
        ngrp = (ci == 0) ? 6 : 5;         // 30 / 25 / 25 pairs
    } else {
        const int q = bid - 24;
        c = 8 + (q >> 2);
        const int ci = q & 3;
        z0 = ci * 40;
        ngrp = 4;                         // 20 pairs
    }
    const int b  = c / (GX * GY);
    const int rr = c - b * (GX * GY);
    const int yt = rr / GX;
    const int xt = rr - yt * GX;
    const int x0 = xt * TX;
    const int y0 = yt * TY;
    const int base = b * (DD * HW);

    // shared-state u32 base for cp.async destinations
    unsigned raw_u32;
    {
        unsigned long long p = (unsigned long long)__cvta_generic_to_shared(dsm + OFF_RAW);
        raw_u32 = (unsigned)p;
    }

    // ---- raw loader mapping: 576 entries over 512 threads ----
    const int row0 = tid / RCOLS, col0 = tid - row0 * RCOLS;
    const int gy0 = y0 + row0 - 2, gx0 = x0 + col0 - 2;
    const bool ok0 = ((unsigned)gy0 < HH) && ((unsigned)gx0 < WW);
    const int pB0 = base + (ok0 ? gy0 * WW + gx0 : 0);
    const unsigned e0off = (unsigned)(row0 * RCOLS + col0) * 8u;

    const bool has1 = (tid < RR * RCOLS - NT);    // 64 extra entries
    const int e1 = tid + NT;
    const int row1 = e1 / RCOLS, col1 = e1 - row1 * RCOLS;
    const int gy1 = y0 + row1 - 2, gx1 = x0 + col1 - 2;
    const bool ok1 = ((unsigned)gy1 < HH) && ((unsigned)gx1 < WW);
    const int pB1 = base + (ok1 ? gy1 * WW + gx1 : 0);
    const unsigned e1off = (unsigned)(row1 * RCOLS + col1) * 8u;

    // ---- xsum entry: one (row, x) per thread ----
    const int xr = warp;            // 0..15
    const int xx = lane;            // 0..31

    // ---- y-emit mapping: 256 threads = 2 slices x 4 row-groups x 32 cols ----
    const bool emit_ok = (tid < 256);
    const int esl = tid >> 7;                   // slice of the pair
    const int eu  = tid & 127;
    const int exx = eu & 31;
    const int g3  = (eu >> 5) * 3;              // output rows g3..g3+2 (0,3,6,9)
    int woff = base + (z0 + esl) * HW + (y0 + g3) * WW + (x0 + exx);

    // ---- z ring (static slots) + running sums ----
    float r0[5] = {0,0,0,0,0}, r1[5] = {0,0,0,0,0}, r2[5] = {0,0,0,0,0};
    float r3[5] = {0,0,0,0,0}, r4[5] = {0,0,0,0,0};
    float SI = 0.f, SJ = 0.f, SII = 0.f, SJJ = 0.f, SIJ = 0.f;
    float acc = 0.f;

    // ---- prologue: slices z0-2, z0-1 into pair 0 (async + wait + barrier) ----
    {
        const int zp = z0 - 2;
        const bool zA = (zp >= 0);
        const bool zB = (zp + 1 >= 0);
        const unsigned dA0 = raw_u32 + e0off;
        const unsigned dB0 = dA0 + RAW_SLICE_BYTES;
        const float* sI0 = gI + pB0 + zp * HW;
        const float* sJ0 = gJ + pB0 + zp * HW;
        cpa4(dA0,     sI0,      zA && ok0);
        cpa4(dA0 + 4, sJ0,      zA && ok0);
        cpa4(dB0,     sI0 + HW, zB && ok0);
        cpa4(dB0 + 4, sJ0 + HW, zB && ok0);
        if (has1) {
            const unsigned dA1 = raw_u32 + e1off;
            const unsigned dB1 = dA1 + RAW_SLICE_BYTES;
            const float* sI1 = gI + pB1 + zp * HW;
            const float* sJ1 = gJ + pB1 + zp * HW;
            cpa4(dA1,     sI1,      zA && ok1);
            cpa4(dA1 + 4, sJ1,      zA && ok1);
            cpa4(dB1,     sI1 + HW, zB && ok1);
            cpa4(dB1 + 4, sJ1 + HW, zB && ok1);
        }
        cpa_wait_all();
        __syncthreads();
    }

    int bi = 0;
    int zpre = z0;               // phase p prefetches slices z0+2p, z0+2p+1
    int preoff = z0 * HW;

    PHASE(0, 1, false);          // XR z0-2, z0-1
    PHASE(2, 3, false);          // XR z0,   z0+1

    // ---- main: ngrp statically-unrolled 5-phase groups (period = 10 slices) ----
#pragma unroll 1
    for (int g = 0; g < ngrp; ++g) {
        PHASE(4, 0, true);
        PHASE(1, 2, true);
        PHASE(3, 4, true);
        PHASE(0, 1, true);
        PHASE(2, 3, true);
    }

    // ---- reduction: shuffle tree (deterministic) ----
    double a = (double)acc;
#pragma unroll
    for (int off = 16; off > 0; off >>= 1)
        a += __shfl_down_sync(0xffffffffu, a, off);
    if (lane == 0) sred[warp] = a;
    __syncthreads();
    if (warp == 0) {
        double s = (lane < 16) ? sred[lane] : 0.0;
#pragma unroll
        for (int off = 8; off > 0; off >>= 1)
            s += __shfl_down_sync(0xffffffffu, s, off);
        if (lane == 0) {
            g_partials[bid] = s;
            __threadfence();
            const unsigned v = atomicAdd(&g_count, 1u);
            *slast = (v == NBLOCKS - 1);
        }
    }
    __syncthreads();

    // ---- last block folds all partials in fixed order ----
    if (*slast) {
        double s = 0.0;
        for (int i = tid; i < NBLOCKS; i += NT) s += g_partials[i];
#pragma unroll
        for (int off = 16; off > 0; off >>= 1)
            s += __shfl_down_sync(0xffffffffu, s, off);
        if (lane == 0) sred[warp] = s;
        __syncthreads();
        if (warp == 0) {
            double t = (lane < 16) ? sred[lane] : 0.0;
#pragma unroll
            for (int off = 8; off > 0; off >>= 1)
                t += __shfl_down_sync(0xffffffffu, t, off);
            if (lane == 0) {
                out[0] = (float)(-t / NTOT);
                g_count = 0;   // reset for next graph replay
            }
        }
    }
}

extern "C" void kernel_launch(void* const* d_in, const int* in_sizes, int n_in,
                              void* d_out, int out_size)
{
    const float* I  = (const float*)d_in[0];
    const float* J  = (const float*)d_in[1];
    const float* Wt = (const float*)d_in[2];
    float* out = (float*)d_out;

    cudaFuncSetAttribute(ncc_fused, cudaFuncAttributeMaxDynamicSharedMemorySize,
                         SMEM_BYTES);
    ncc_fused<<<NBLOCKS, NT, SMEM_BYTES>>>(I, J, Wt, out);
}

// round 17
// speedup vs baseline: 1.2670x; 1.0160x over previous
#include <cuda_runtime.h>

// Shape (B=2, C=1, D=160, H=192, W=224), win=5, eps=1e-8
#define DD 160
#define HH 192
#define WW 224
#define BB 2
#define HW (HH * WW)
#define TX 32
#define TY 12
#define RR 16                    // rows per block = TY + 4
#define RCOLS 36                 // halo cols = TX + 4
#define GX (WW / TX)             // 7
#define GY (HH / TY)             // 16
#define NBLOCKS 888              // == 296 * 3 : exact multiple of chip concurrency
#define NT 512
#define NTOT ((double)BB * DD * HH * WW)

// raw ring: 3 pair-buffers
#define PAIR_F2   (2 * RR * RCOLS)             // float2 elements per pair buffer
#define RAW_PAIR_BYTES  9216                   // float2 [2][RR][RCOLS]
#define RAW_SLICE_BYTES 4608                   // float2 [RR][RCOLS]
#define OFF_RAW   0                            // float2 [3][2][RR][RCOLS] = 27648
#define OFF_ZS4   27648                        // float4 [2][2][RR][TX]   = 32768
#define OFF_ZS1   (27648 + 32768)              // float  [2][2][RR][TX]   = 8192
#define OFF_SRED  (27648 + 32768 + 8192)       // double [16]             = 128
#define OFF_LAST  (OFF_SRED + 128)             // int
#define SMEM_BYTES (OFF_LAST + 16)

__device__ double g_partials[NBLOCKS];
__device__ unsigned int g_count = 0;

// 4-byte async copy global->shared with zero-fill when pred is false
__device__ __forceinline__ void cpa4(unsigned dst, const float* src, bool pred)
{
    const int sz = pred ? 4 : 0;
    asm volatile("cp.async.ca.shared.global [%0], [%1], 4, %2;"
                 :: "r"(dst), "l"(src), "r"(sz) : "memory");
}
__device__ __forceinline__ void cpa_commit()
{
    asm volatile("cp.async.commit_group;" ::: "memory");
}
__device__ __forceinline__ void cpa_wait1()
{
    asm volatile("cp.async.wait_group 1;" ::: "memory");
}

__device__ __forceinline__ float ncc_cc(float4 s, float sij)
{
    const float wsz = 125.0f, inv = 1.0f / 125.0f;
    const float uI = s.x * inv, uJ = s.y * inv;
    const float cross = sij - uJ * s.x - uI * s.y + uI * uJ * wsz;
    const float Iv = s.z - 2.0f * uI * s.x + uI * uI * wsz;
    const float Jv = s.w - 2.0f * uJ * s.y + uJ * uJ * wsz;
    return __fdividef(cross * cross, Iv * Jv + 1e-8f);
}

// x-box sums + z-ring update for one slice S (0/1) of read pair rp.
#define XR(SLOT, S) do {                                                        \
    float2 v0 = rp[(S) * (RR * RCOLS) + xoff + 0];                              \
    float2 v1 = rp[(S) * (RR * RCOLS) + xoff + 1];                              \
    float2 v2 = rp[(S) * (RR * RCOLS) + xoff + 2];                              \
    float2 v3 = rp[(S) * (RR * RCOLS) + xoff + 3];                              \
    float2 v4 = rp[(S) * (RR * RCOLS) + xoff + 4];                              \
    const float a0 = v0.x + v1.x + v2.x + v3.x + v4.x;                          \
    const float a1 = v0.y + v1.y + v2.y + v3.y + v4.y;                          \
    const float a2 = fmaf(v4.x, v4.x, fmaf(v3.x, v3.x,                          \
                     fmaf(v2.x, v2.x, fmaf(v1.x, v1.x, v0.x * v0.x))));         \
    const float a3 = fmaf(v4.y, v4.y, fmaf(v3.y, v3.y,                          \
                     fmaf(v2.y, v2.y, fmaf(v1.y, v1.y, v0.y * v0.y))));         \
    const float a4 = fmaf(v4.x, v4.y, fmaf(v3.x, v3.y,                          \
                     fmaf(v2.x, v2.y, fmaf(v1.x, v1.y, v0.x * v0.y))));         \
    SI  += a0 - r0[SLOT]; r0[SLOT] = a0;                                        \
    SJ  += a1 - r1[SLOT]; r1[SLOT] = a1;                                        \
    SII += a2 - r2[SLOT]; r2[SLOT] = a2;                                        \
    SJJ += a3 - r3[SLOT]; r3[SLOT] = a3;                                        \
    SIJ += a4 - r4[SLOT]; r4[SLOT] = a4;                                        \
    zs4[bz][S][xr][xx] = make_float4(SI, SJ, SII, SJJ);                         \
    zs1[bz][S][xr][xx] = SIJ;                                                   \
} while (0)

// One phase = two z-slices, one barrier. SA/SB/DOY compile-time literals.
// Reads pair at rp; issues 2-ahead fill into fladdr; waits the 1-ahead group.
#define PHASE(SA, SB, DOY) do {                                                 \
    {   /* async fill (2 phases ahead) of slices (zpre, zpre+1), zfill OOB */   \
        const bool zA = (zpre < DD), zB = (zpre + 1 < DD);                      \
        const unsigned dA0 = fladdr + e0off;                                    \
        const unsigned dB0 = dA0 + RAW_SLICE_BYTES;                             \
        const float* sI0 = gI + pB0 + preoff;                                   \
        const float* sJ0 = gJ + pB0 + preoff;                                   \
        cpa4(dA0,     sI0,      zA && ok0);                                     \
        cpa4(dA0 + 4, sJ0,      zA && ok0);                                     \
        cpa4(dB0,     sI0 + HW, zB && ok0);                                     \
        cpa4(dB0 + 4, sJ0 + HW, zB && ok0);                                     \
        if (has1) {                                                             \
            const unsigned dA1 = fladdr + e1off;                                \
            const unsigned dB1 = dA1 + RAW_SLICE_BYTES;                         \
            const float* sI1 = gI + pB1 + preoff;                               \
            const float* sJ1 = gJ + pB1 + preoff;                               \
            cpa4(dA1,     sI1,      zA && ok1);                                 \
            cpa4(dA1 + 4, sJ1,      zA && ok1);                                 \
            cpa4(dB1,     sI1 + HW, zB && ok1);                                 \
            cpa4(dB1 + 4, sJ1 + HW, zB && ok1);                                 \
        }                                                                       \
        cpa_commit();                                                           \
    }                                                                           \
    float w0 = 0.f, w1 = 0.f;                                                   \
    if (DOY && emit_ok) { w0 = gW[woff]; w1 = gW[woff + WW]; }                  \
    XR(SA, 0);                                                                  \
    XR(SB, 1);                                                                  \
    cpa_wait1();                                                                \
    __syncthreads();                                                            \
    if (DOY && emit_ok) {                                                       \
        float4 sA = make_float4(0.f, 0.f, 0.f, 0.f);                            \
        float4 sB = make_float4(0.f, 0.f, 0.f, 0.f);                            \
        float sA1 = 0.f, sB1 = 0.f;                                             \
        _Pragma("unroll")                                                       \
        for (int j = 0; j < 6; ++j) {                                           \
            float4 v = zs4[bz][esl][yb + j][exx];                               \
            float  u = zs1[bz][esl][yb + j][exx];                               \
            if (j < 5) { sA.x += v.x; sA.y += v.y; sA.z += v.z; sA.w += v.w;    \
                         sA1 += u; }                                            \
            if (j > 0) { sB.x += v.x; sB.y += v.y; sB.z += v.z; sB.w += v.w;    \
                         sB1 += u; }                                            \
        }                                                                       \
        acc = fmaf(ncc_cc(sA, sA1), w0, acc);                                   \
        acc = fmaf(ncc_cc(sB, sB1), w1, acc);                                   \
        woff += 2 * HW;                                                         \
    }                                                                           \
    /* advance ring state */                                                    \
    rp += PAIR_F2;        if (rp == rp_end)      rp = rp_base;                  \
    fladdr += RAW_PAIR_BYTES; if (fladdr == fl_end) fladdr = raw_u32;           \
    bz ^= 1;                                                                    \
    zpre += 2; preoff += 2 * HW;                                                \
} while (0)

__global__ __launch_bounds__(NT, 2)
void ncc_fused(const float* __restrict__ gI,
               const float* __restrict__ gJ,
               const float* __restrict__ gW,
               float* __restrict__ out)
{
    extern __shared__ unsigned char dsm[];
    float4 (*zs4)[2][RR][TX]     = (float4 (*)[2][RR][TX])(dsm + OFF_ZS4);
    float  (*zs1)[2][RR][TX]     = (float  (*)[2][RR][TX])(dsm + OFF_ZS1);
    double* sred  = (double*)(dsm + OFF_SRED);
    int*    slast = (int*)(dsm + OFF_LAST);

    const int tid  = threadIdx.x;
    const int lane = tid & 31;
    const int warp = tid >> 5;

    // ---- block schedule decode: 888 blocks over 224 (x,y,b) columns ----
    // blocks 0..23  : 8 special columns x 3 chunks, z0={0,60,110}, len={60,50,50}
    // blocks 24..887: 216 regular columns x 4 chunks of len 40
    const int bid = blockIdx.x;
    int c, z0, ngrp;                      // ngrp = npairs/5
    if (bid < 24) {
        c = bid / 3;
        const int ci = bid - c * 3;
        z0   = (ci == 0) ? 0 : (ci == 1 ? 60 : 110);
        ngrp = (ci == 0) ? 6 : 5;         // 30 / 25 / 25 pairs
    } else {
        const int q = bid - 24;
        c = 8 + (q >> 2);
        const int ci = q & 3;
        z0 = ci * 40;
        ngrp = 4;                         // 20 pairs
    }
    const int b  = c / (GX * GY);
    const int rr = c - b * (GX * GY);
    const int yt = rr / GX;
    const int xt = rr - yt * GX;
    const int x0 = xt * TX;
    const int y0 = yt * TY;
    const int base = b * (DD * HW);

    // raw ring pointers
    const float2* rp_base = (const float2*)(dsm + OFF_RAW);
    const float2* rp_end  = rp_base + 3 * PAIR_F2;
    const float2* rp      = rp_base;
    unsigned raw_u32;
    {
        unsigned long long p = (unsigned long long)__cvta_generic_to_shared(dsm + OFF_RAW);
        raw_u32 = (unsigned)p;
    }
    const unsigned fl_end = raw_u32 + 3 * RAW_PAIR_BYTES;

    // ---- raw loader mapping: 576 entries over 512 threads ----
    const int row0 = tid / RCOLS, col0 = tid - row0 * RCOLS;
    const int gy0 = y0 + row0 - 2, gx0 = x0 + col0 - 2;
    const bool ok0 = ((unsigned)gy0 < HH) && ((unsigned)gx0 < WW);
    const int pB0 = base + (ok0 ? gy0 * WW + gx0 : 0);
    const unsigned e0off = (unsigned)(row0 * RCOLS + col0) * 8u;

    const bool has1 = (tid < RR * RCOLS - NT);    // 64 extra entries
    const int e1 = tid + NT;
    const int row1 = e1 / RCOLS, col1 = e1 - row1 * RCOLS;
    const int gy1 = y0 + row1 - 2, gx1 = x0 + col1 - 2;
    const bool ok1 = ((unsigned)gy1 < HH) && ((unsigned)gx1 < WW);
    const int pB1 = base + (ok1 ? gy1 * WW + gx1 : 0);
    const unsigned e1off = (unsigned)(row1 * RCOLS + col1) * 8u;

    // ---- xsum entry: one (row, x) per thread ----
    const int xr = warp;            // 0..15
    const int xx = lane;            // 0..31
    const int xoff = xr * RCOLS + xx;

    // ---- y-emit mapping: 384 threads, 2 slices x 192 ----
    const bool emit_ok = (tid < 384);
    const int esl = tid / 192;                 // slice of the pair
    const int eu  = tid - esl * 192;
    const int exx = eu & 31;
    const int yb  = (eu >> 5) * 2;             // 0,2,..,10
    int woff = base + (z0 + esl) * HW + (y0 + yb) * WW + (x0 + exx);

    // ---- z ring (static slots) + running sums ----
    float r0[5] = {0,0,0,0,0}, r1[5] = {0,0,0,0,0}, r2[5] = {0,0,0,0,0};
    float r3[5] = {0,0,0,0,0}, r4[5] = {0,0,0,0,0};
    float SI = 0.f, SJ = 0.f, SII = 0.f, SJJ = 0.f, SIJ = 0.f;
    float acc = 0.f;

    // ---- prologue: fill buf0 (pair z0-2) and buf1 (pair z0), wait buf0 ----
    {
        // buf0: slices z0-2, z0-1
        const int zp = z0 - 2;
        const bool zA = (zp >= 0), zB = (zp + 1 >= 0);
        const unsigned dA0 = raw_u32 + e0off;
        const unsigned dB0 = dA0 + RAW_SLICE_BYTES;
        const float* sI0 = gI + pB0 + zp * HW;
        const float* sJ0 = gJ + pB0 + zp * HW;
        cpa4(dA0,     sI0,      zA && ok0);
        cpa4(dA0 + 4, sJ0,      zA && ok0);
        cpa4(dB0,     sI0 + HW, zB && ok0);
        cpa4(dB0 + 4, sJ0 + HW, zB && ok0);
        if (has1) {
            const unsigned dA1 = raw_u32 + e1off;
            const unsigned dB1 = dA1 + RAW_SLICE_BYTES;
            const float* sI1 = gI + pB1 + zp * HW;
            const float* sJ1 = gJ + pB1 + zp * HW;
            cpa4(dA1,     sI1,      zA && ok1);
            cpa4(dA1 + 4, sJ1,      zA && ok1);
            cpa4(dB1,     sI1 + HW, zB && ok1);
            cpa4(dB1 + 4, sJ1 + HW, zB && ok1);
        }
        cpa_commit();
        // buf1: slices z0, z0+1 (always in range)
        const unsigned fB = raw_u32 + RAW_PAIR_BYTES;
        const unsigned dA0b = fB + e0off;
        const unsigned dB0b = dA0b + RAW_SLICE_BYTES;
        const float* sI0b = gI + pB0 + z0 * HW;
        const float* sJ0b = gJ + pB0 + z0 * HW;
        cpa4(dA0b,     sI0b,      ok0);
        cpa4(dA0b + 4, sJ0b,      ok0);
        cpa4(dB0b,     sI0b + HW, ok0);
        cpa4(dB0b + 4, sJ0b + HW, ok0);
        if (has1) {
            const unsigned dA1b = fB + e1off;
            const unsigned dB1b = dA1b + RAW_SLICE_BYTES;
            const float* sI1b = gI + pB1 + z0 * HW;
            const float* sJ1b = gJ + pB1 + z0 * HW;
            cpa4(dA1b,     sI1b,      ok1);
            cpa4(dA1b + 4, sJ1b,      ok1);
            cpa4(dB1b,     sI1b + HW, ok1);
            cpa4(dB1b + 4, sJ1b + HW, ok1);
        }
        cpa_commit();
        cpa_wait1();               // buf0 ready; buf1 may still be in flight
        __syncthreads();
    }

    int bz = 0;                       // zs parity
    unsigned fladdr = raw_u32 + 2 * RAW_PAIR_BYTES;   // fill target = buf2
    int zpre = z0 + 2;                // phase p fills slices z0+2p+2, z0+2p+3
    int preoff = (z0 + 2) * HW;

    PHASE(0, 1, false);          // XR z0-2, z0-1 (buf0)
    PHASE(2, 3, false);          // XR z0,   z0+1 (buf1)

    // ---- main: ngrp statically-unrolled 5-phase groups (period = 10 slices) ----
#pragma unroll 1
    for (int g = 0; g < ngrp; ++g) {
        PHASE(4, 0, true);
        PHASE(1, 2, true);
        PHASE(3, 4, true);
        PHASE(0, 1, true);
        PHASE(2, 3, true);
    }

    // ---- reduction: shuffle tree (deterministic) ----
    double a = (double)acc;
#pragma unroll
    for (int off = 16; off > 0; off >>= 1)
        a += __shfl_down_sync(0xffffffffu, a, off);
    if (lane == 0) sred[warp] = a;
    __syncthreads();
    if (warp == 0) {
        double s = (lane < 16) ? sred[lane] : 0.0;
#pragma unroll
        for (int off = 8; off > 0; off >>= 1)
            s += __shfl_down_sync(0xffffffffu, s, off);
        if (lane == 0) {
            g_partials[bid] = s;
            __threadfence();
            const unsigned v = atomicAdd(&g_count, 1u);
            *slast = (v == NBLOCKS - 1);
        }
    }
    __syncthreads();

    // ---- last block folds all partials in fixed order ----
    if (*slast) {
        double s = 0.0;
        for (int i = tid; i < NBLOCKS; i += NT) s += g_partials[i];
#pragma unroll
        for (int off = 16; off > 0; off >>= 1)
            s += __shfl_down_sync(0xffffffffu, s, off);
        if (lane == 0) sred[warp] = s;
        __syncthreads();
        if (warp == 0) {
            double t = (lane < 16) ? sred[lane] : 0.0;
#pragma unroll
            for (int off = 8; off > 0; off >>= 1)
                t += __shfl_down_sync(0xffffffffu, t, off);
            if (lane == 0) {
                out[0] = (float)(-t / NTOT);
                g_count = 0;   // reset for next graph replay
            }
        }
    }
}

extern "C" void kernel_launch(void* const* d_in, const int* in_sizes, int n_in,
                              void* d_out, int out_size)
{
    const float* I  = (const float*)d_in[0];
    const float* J  = (const float*)d_in[1];
    const float* Wt = (const float*)d_in[2];
    float* out = (float*)d_out;

    cudaFuncSetAttribute(ncc_fused, cudaFuncAttributeMaxDynamicSharedMemorySize,
                         SMEM_BYTES);
    ncc_fused<<<NBLOCKS, NT, SMEM_BYTES>>>(I, J, Wt, out);
}